// round 2
// baseline (speedup 1.0000x reference)
#include <cuda_runtime.h>
#include <cuda_bf16.h>
#include <cstdint>

// Problem constants
#define BSZ   256
#define HID   1024
#define TSTEPS 64
#define N4    4096          // 4*HID
#define OUTW  64
#define INLEN 512

// GEMM tiling
#define BM 128
#define BN 64
#define BK 32
#define SSTRIDE 36                       // 32 data + 4 pad floats (16B aligned, conflict-free)
#define A_TILE_F (BM * SSTRIDE)          // 4608 floats
#define B_TILE_F (BN * SSTRIDE)          // 2304 floats
#define STAGE_F  (A_TILE_F + B_TILE_F)   // 6912 floats
#define SMEM_BYTES (2 * STAGE_F * 4)     // 55296 bytes
#define CSTRIDE 68                       // epilogue C stride (float4-aligned rows)

// ---------------- device scratch (static allocation only) ----------------
__device__ float g_Whp[N4 * HID];        // permuted w_hh            (step 0)
__device__ float g_Wcp[N4 * HID];        // permuted w_ih + w_hh     (steps >=1)
__device__ float g_g0[N4];               // step-0 bias: st@w_ihT + b_ih + b_hh (permuted)
__device__ float g_bp[N4];               // b_ih + b_hh (permuted)
__device__ float g_act0[BSZ * HID];      // ping-pong tf32-rounded activations
__device__ float g_act1[BSZ * HID];
__device__ float g_c[BSZ * HID];         // cell state
__device__ float g_out[BSZ * TSTEPS * HID]; // hidden outputs [b][t][h]

// ---------------- helpers ----------------
__device__ __forceinline__ float tf32r(float x) {
    uint32_t u;
    asm("cvt.rna.tf32.f32 %0, %1;" : "=r"(u) : "f"(x));
    return __uint_as_float(u);
}
__device__ __forceinline__ float sigm(float x) { return 1.0f / (1.0f + __expf(-x)); }
__device__ __forceinline__ float tanh_acc(float x) { return 2.0f / (1.0f + __expf(-2.0f * x)) - 1.0f; }

__device__ __forceinline__ void cp16(float* dst_smem, const float* src) {
    uint32_t d = (uint32_t)__cvta_generic_to_shared(dst_smem);
    asm volatile("cp.async.cg.shared.global [%0], [%1], 16;\n" :: "r"(d), "l"(src));
}
__device__ __forceinline__ void mma_tf32(float* c, const uint32_t* a, const uint32_t* b) {
    asm volatile(
        "mma.sync.aligned.m16n8k8.row.col.f32.tf32.tf32.f32 "
        "{%0,%1,%2,%3}, {%4,%5,%6,%7}, {%8,%9}, {%0,%1,%2,%3};\n"
        : "+f"(c[0]), "+f"(c[1]), "+f"(c[2]), "+f"(c[3])
        : "r"(a[0]), "r"(a[1]), "r"(a[2]), "r"(a[3]), "r"(b[0]), "r"(b[1]));
}

// ---------------- prep: permuted weights ----------------
// n' = 4*h + g ; j = g*HID + h
__global__ void prep_weights(const float* __restrict__ w_ih, const float* __restrict__ w_hh) {
    int idx = blockIdx.x * 256 + threadIdx.x;       // over N4*HID
    int np = idx >> 10;
    int k  = idx & 1023;
    int h  = np >> 2;
    int g  = np & 3;
    int j  = (g << 10) + h;
    float a = w_ih[j * HID + k];
    float b = w_hh[j * HID + k];
    g_Whp[idx] = tf32r(b);
    g_Wcp[idx] = tf32r(a + b);
}

// g0[n'] = dot(start_token, w_ih[j]) + b_ih[j] + b_hh[j]; bp[n'] = b_ih[j] + b_hh[j]
__global__ void prep_bias(const float* __restrict__ st, const float* __restrict__ w_ih,
                          const float* __restrict__ b_ih, const float* __restrict__ b_hh) {
    int gw   = (blockIdx.x * blockDim.x + threadIdx.x) >> 5;  // global warp id (1024 warps)
    int lane = threadIdx.x & 31;
    for (int np = gw; np < N4; np += 1024) {
        int h = np >> 2, g = np & 3;
        int j = (g << 10) + h;
        const float* wr = w_ih + (size_t)j * HID;
        float s = 0.f;
        #pragma unroll 8
        for (int k = lane; k < HID; k += 32) s += st[k] * wr[k];
        #pragma unroll
        for (int off = 16; off > 0; off >>= 1) s += __shfl_xor_sync(0xffffffffu, s, off);
        if (lane == 0) {
            float bs = b_ih[j] + b_hh[j];
            g_bp[np] = bs;
            g_g0[np] = s + bs;
        }
    }
}

// ---------------- h0 = qf_encoded contracted over input_len ----------------
__global__ void h0_kernel(const float* __restrict__ qf, const float* __restrict__ w_in,
                          const float* __restrict__ b_in) {
    __shared__ float sw[INLEN];
    int b = blockIdx.x;
    int tid = threadIdx.x;                 // 256 threads, thread t -> float4 at h = 4t
    sw[tid] = w_in[tid];
    sw[tid + 256] = w_in[tid + 256];
    __syncthreads();
    const float4* q = reinterpret_cast<const float4*>(qf) + (size_t)b * INLEN * (HID / 4) + tid;
    float4 acc = make_float4(0.f, 0.f, 0.f, 0.f);
    #pragma unroll 8
    for (int i = 0; i < INLEN; i++) {
        float4 v = q[(size_t)i * (HID / 4)];
        float w = sw[i];
        acc.x = fmaf(v.x, w, acc.x);
        acc.y = fmaf(v.y, w, acc.y);
        acc.z = fmaf(v.z, w, acc.z);
        acc.w = fmaf(v.w, w, acc.w);
    }
    float bb = b_in[0];
    int base = b * HID + tid * 4;
    g_act0[base + 0] = tf32r(acc.x + bb);
    g_act0[base + 1] = tf32r(acc.y + bb);
    g_act0[base + 2] = tf32r(acc.z + bb);
    g_act0[base + 3] = tf32r(acc.w + bb);
    *reinterpret_cast<float4*>(&g_c[base]) = make_float4(0.f, 0.f, 0.f, 0.f);
}

// ---------------- fused GEMM (+LSTM cell or +linear) ----------------
// mode 0: LSTM step.  A[M=256,K]@W[N=4096,K]T (gate-interleaved N), cell epilogue.
// mode 1: projection. A[M=16384,K]@W[N=64,K]T, +bias epilogue to dst.
extern __shared__ float smem[];

__global__ void __launch_bounds__(256)
gemm_step(const float* __restrict__ A, const float* __restrict__ W,
          const float* __restrict__ bias, float* __restrict__ act_out,
          float* __restrict__ dst, int mode, int t) {
    const int tid  = threadIdx.x;
    const int lane = tid & 31;
    const int w    = tid >> 5;
    const int wm   = w & 3;         // warp grid 4(m) x 2(n)
    const int wn   = w >> 2;
    const int mOff = wm * 32;
    const int nOff = wn * 32;
    const int mBase = blockIdx.x * BM;
    const int nBase = blockIdx.y * BN;

    float acc[2][4][4];
    #pragma unroll
    for (int i = 0; i < 2; i++)
        #pragma unroll
        for (int j = 0; j < 4; j++)
            #pragma unroll
            for (int r = 0; r < 4; r++) acc[i][j][r] = 0.f;

    // chunk decomposition for staging: 8 chunks of 16B per 32-float row
    const int chA_r[4] = { (tid + 0) >> 3, (tid + 256) >> 3, (tid + 512) >> 3, (tid + 768) >> 3 };
    const int chA_c[4] = { (tid & 7) << 2, (tid & 7) << 2, (tid & 7) << 2, (tid & 7) << 2 };

    auto stage = [&](int kt, int s) {
        float* sA = smem + s * STAGE_F;
        float* sB = sA + A_TILE_F;
        int kBase = kt * BK;
        #pragma unroll
        for (int i = 0; i < 4; i++) {
            int r = chA_r[i], cc = chA_c[i];
            cp16(sA + r * SSTRIDE + cc, A + (size_t)(mBase + r) * HID + kBase + cc);
        }
        #pragma unroll
        for (int i = 0; i < 2; i++) {
            int ch = tid + i * 256;
            int r = ch >> 3, cc = (ch & 7) << 2;
            cp16(sB + r * SSTRIDE + cc, W + (size_t)(nBase + r) * HID + kBase + cc);
        }
    };

    const int NKT = HID / BK;   // 32
    stage(0, 0);
    asm volatile("cp.async.commit_group;\n");

    for (int kt = 0; kt < NKT; kt++) {
        __syncthreads();   // prior compute done before overwriting next stage
        if (kt + 1 < NKT) {
            stage(kt + 1, (kt + 1) & 1);
            asm volatile("cp.async.commit_group;\n");
            asm volatile("cp.async.wait_group 1;\n");
        } else {
            asm volatile("cp.async.wait_group 0;\n");
        }
        __syncthreads();

        const float* sA = smem + (kt & 1) * STAGE_F;
        const float* sB = sA + A_TILE_F;

        #pragma unroll
        for (int ks = 0; ks < 4; ks++) {
            const int kc = ks * 8 + (lane & 3);
            uint32_t af[2][4];
            #pragma unroll
            for (int mb = 0; mb < 2; mb++) {
                int r = mOff + mb * 16 + (lane >> 2);
                af[mb][0] = __float_as_uint(sA[r * SSTRIDE + kc]);
                af[mb][1] = __float_as_uint(sA[(r + 8) * SSTRIDE + kc]);
                af[mb][2] = __float_as_uint(sA[r * SSTRIDE + kc + 4]);
                af[mb][3] = __float_as_uint(sA[(r + 8) * SSTRIDE + kc + 4]);
            }
            uint32_t bf[4][2];
            #pragma unroll
            for (int nb = 0; nb < 4; nb++) {
                int n = nOff + nb * 8 + (lane >> 2);
                bf[nb][0] = __float_as_uint(sB[n * SSTRIDE + kc]);
                bf[nb][1] = __float_as_uint(sB[n * SSTRIDE + kc + 4]);
            }
            #pragma unroll
            for (int mb = 0; mb < 2; mb++)
                #pragma unroll
                for (int nb = 0; nb < 4; nb++)
                    mma_tf32(acc[mb][nb], af[mb], bf[nb]);
        }
    }

    // stash C to smem
    __syncthreads();
    float* Cs = smem;
    #pragma unroll
    for (int mb = 0; mb < 2; mb++)
        #pragma unroll
        for (int nb = 0; nb < 4; nb++) {
            int r = mOff + mb * 16 + (lane >> 2);
            int cc = nOff + nb * 8 + (lane & 3) * 2;
            Cs[r * CSTRIDE + cc]            = acc[mb][nb][0];
            Cs[r * CSTRIDE + cc + 1]        = acc[mb][nb][1];
            Cs[(r + 8) * CSTRIDE + cc]      = acc[mb][nb][2];
            Cs[(r + 8) * CSTRIDE + cc + 1]  = acc[mb][nb][3];
        }
    __syncthreads();

    if (mode == 0) {
        // LSTM cell: 128 rows x 16 h-groups
        for (int idx = tid; idx < BM * (BN / 4); idx += 256) {
            int row = idx >> 4, hh = idx & 15;
            int b = mBase + row;
            int hg = (nBase >> 2) + hh;
            float4 gv = *reinterpret_cast<const float4*>(&Cs[row * CSTRIDE + hh * 4]);
            float4 bb = *reinterpret_cast<const float4*>(&bias[nBase + hh * 4]);
            float gi = gv.x + bb.x;
            float gf = gv.y + bb.y;
            float gg = gv.z + bb.z;
            float go = gv.w + bb.w;
            float cOld = g_c[b * HID + hg];
            float cN = sigm(gf) * cOld + sigm(gi) * tanh_acc(gg);
            float hN = sigm(go) * tanh_acc(cN);
            g_c[b * HID + hg] = cN;
            g_out[((size_t)b * TSTEPS + t) * HID + hg] = hN;
            act_out[b * HID + hg] = tf32r(hN);
        }
    } else {
        for (int idx = tid; idx < BM * BN; idx += 256) {
            int row = idx >> 6, col = idx & 63;
            int rb = mBase + row;
            dst[(size_t)rb * OUTW + col] = Cs[row * CSTRIDE + col] + bias[col];
        }
    }
}

// ---------------- host ----------------
extern "C" void kernel_launch(void* const* d_in, const int* in_sizes, int n_in,
                              void* d_out, int out_size) {
    const float* qf    = (const float*)d_in[1];
    const float* st    = (const float*)d_in[4];
    const float* w_in  = (const float*)d_in[5];
    const float* b_in  = (const float*)d_in[6];
    const float* w_ih  = (const float*)d_in[7];
    const float* w_hh  = (const float*)d_in[8];
    const float* b_ih  = (const float*)d_in[9];
    const float* b_hh  = (const float*)d_in[10];
    const float* w_out = (const float*)d_in[11];
    const float* b_out = (const float*)d_in[12];
    float* out = (float*)d_out;

    float *p_Whp, *p_Wcp, *p_g0, *p_bp, *p_act0, *p_act1, *p_hout;
    cudaGetSymbolAddress((void**)&p_Whp, g_Whp);
    cudaGetSymbolAddress((void**)&p_Wcp, g_Wcp);
    cudaGetSymbolAddress((void**)&p_g0,  g_g0);
    cudaGetSymbolAddress((void**)&p_bp,  g_bp);
    cudaGetSymbolAddress((void**)&p_act0, g_act0);
    cudaGetSymbolAddress((void**)&p_act1, g_act1);
    cudaGetSymbolAddress((void**)&p_hout, g_out);

    cudaFuncSetAttribute(gemm_step, cudaFuncAttributeMaxDynamicSharedMemorySize, SMEM_BYTES);

    prep_weights<<<(N4 * HID) / 256, 256>>>(w_ih, w_hh);
    prep_bias<<<128, 256>>>(st, w_ih, b_ih, b_hh);
    h0_kernel<<<BSZ, 256>>>(qf, w_in, b_in);

    // recurrence: 64 fused GEMM+cell steps (ping-pong activations)
    for (int t = 0; t < TSTEPS; t++) {
        const float* Ain  = (t & 1) ? p_act1 : p_act0;
        float*       Aout = (t & 1) ? p_act0 : p_act1;
        const float* Wp   = (t == 0) ? p_Whp : p_Wcp;
        const float* bp   = (t == 0) ? p_g0  : p_bp;
        gemm_step<<<dim3(BSZ / BM, N4 / BN), 256, SMEM_BYTES>>>(
            Ain, Wp, bp, Aout, nullptr, 0, t);
    }

    // output handling: reference returns (probs, output)
    const long long PROBS_N = (long long)BSZ * TSTEPS * OUTW;          // 1,048,576
    const long long OUT_N   = (long long)BSZ * TSTEPS * HID;           // 16,777,216
    float* probs_dst = nullptr;
    bool copy_hidden = false;
    long long hidden_off = 0;
    if ((long long)out_size >= PROBS_N + OUT_N) {
        probs_dst = out;
        copy_hidden = true;
        hidden_off = PROBS_N;
    } else if ((long long)out_size == OUT_N) {
        copy_hidden = true;
    } else {
        probs_dst = out;
    }

    if (probs_dst) {
        gemm_step<<<dim3((BSZ * TSTEPS) / BM, 1), 256, SMEM_BYTES>>>(
            p_hout, w_out, b_out, nullptr, probs_dst, 1, 0);
    }
    if (copy_hidden) {
        cudaMemcpyAsync(out + hidden_off, p_hout, OUT_N * sizeof(float),
                        cudaMemcpyDeviceToDevice);
    }
}

// round 3
// speedup vs baseline: 1.2232x; 1.2232x over previous
#include <cuda_runtime.h>
#include <cuda_bf16.h>
#include <cstdint>

// Problem constants
#define BSZ    256
#define HID    1024
#define TSTEPS 64
#define N4     4096
#define OUTW   64
#define INLEN  512
#define K8     (HID / 8)          // 128 k8-chunks

// GEMM tiling
#define BM 128
#define BN 64
#define BK 32
#define NKT (HID / BK)            // 32
#define STAGE_F 6144              // 4096 (A) + 2048 (B) floats per stage
#define NSLOT 3
#define SMEM_BYTES (NSLOT * STAGE_F * 4)   // 73728
#define CSTRIDE 68

// Permuted layout strides (floats)
#define A_MT_STRIDE (K8 * 8 * 32 * 4)     // 131072 floats per 128-row m-tile
#define W_NT_STRIDE (K8 * 8 * 32 * 2)     // 65536  floats per 64-col n-tile

// ---------------- device scratch ----------------
__device__ float  g_Whp[N4 * HID];          // permuted w_hh          (step 0)
__device__ float  g_Wcp[N4 * HID];          // permuted w_ih + w_hh   (steps >=1)
__device__ float  g_WoutP[OUTW * HID];      // permuted w_out
__device__ float  g_g0[N4];
__device__ float  g_bp[N4];
__device__ float  g_act0[BSZ * HID];        // perm activations (ping)
__device__ float  g_act1[BSZ * HID];        // perm activations (pong)
__device__ float  g_c[BSZ * HID];           // cell state (row-major)
__device__ float  g_out[BSZ * TSTEPS * HID];        // hiddens row-major [b][t][h]
__device__ float  g_A2[BSZ * TSTEPS * HID];         // hiddens perm (projection A)
__device__ float4 g_part4[4 * BSZ * (HID / 4)];     // h0 partials

// ---------------- helpers ----------------
__device__ __forceinline__ float tf32r(float x) {
    uint32_t u;
    asm("cvt.rna.tf32.f32 %0, %1;" : "=r"(u) : "f"(x));
    return __uint_as_float(u);
}
__device__ __forceinline__ float sigm(float x) { return 1.0f / (1.0f + __expf(-x)); }
__device__ __forceinline__ float tanh_acc(float x) { return 2.0f / (1.0f + __expf(-2.0f * x)) - 1.0f; }

// A-side permuted index: layout [mt][kc][mb8][lane32][4]
__device__ __forceinline__ size_t aperm_idx(int r, int k) {
    int mt = r >> 7, rr = r & 127;
    int mb = rr >> 4, rl = rr & 15;
    int half  = rl >> 3;
    int lane  = ((rl & 7) << 2) | (k & 3);
    int kc    = k >> 3;
    int khalf = (k >> 2) & 1;
    return ((((size_t)mt * K8 + kc) * 8 + mb) * 32 + lane) * 4 + khalf * 2 + half;
}

__device__ __forceinline__ void cp16(float* dst_smem, const float* src) {
    uint32_t d = (uint32_t)__cvta_generic_to_shared(dst_smem);
    asm volatile("cp.async.cg.shared.global [%0], [%1], 16;\n" :: "r"(d), "l"(src));
}
__device__ __forceinline__ void mma_tf32(float* c, const float4& a, const float2& b) {
    asm volatile(
        "mma.sync.aligned.m16n8k8.row.col.f32.tf32.tf32.f32 "
        "{%0,%1,%2,%3}, {%4,%5,%6,%7}, {%8,%9}, {%0,%1,%2,%3};\n"
        : "+f"(c[0]), "+f"(c[1]), "+f"(c[2]), "+f"(c[3])
        : "r"(__float_as_uint(a.x)), "r"(__float_as_uint(a.y)),
          "r"(__float_as_uint(a.z)), "r"(__float_as_uint(a.w)),
          "r"(__float_as_uint(b.x)), "r"(__float_as_uint(b.y)));
}

// ---------------- prep: permuted weights (coalesced writes) ----------------
// output position gid = (((nt*K8 + kc)*8 + nbi)*32 + lane); each holds 2 floats (khalf 0/1)
__global__ void prep_weights(const float* __restrict__ w_ih, const float* __restrict__ w_hh) {
    int gid  = blockIdx.x * 256 + threadIdx.x;     // 64*128*8*32 = 2,097,152 positions
    int lane = gid & 31;
    int nbi  = (gid >> 5) & 7;
    int kc   = (gid >> 8) & 127;
    int nt   = gid >> 15;
    int np   = nt * 64 + nbi * 8 + (lane >> 2);    // permuted n' = 4h+g
    int h = np >> 2, g = np & 3;
    int j = (g << 10) + h;
    int k0 = kc * 8 + (lane & 3);
    const float* rih = w_ih + (size_t)j * HID;
    const float* rhh = w_hh + (size_t)j * HID;
    float h0v = rhh[k0], h1v = rhh[k0 + 4];
    float c0v = rih[k0] + h0v, c1v = rih[k0 + 4] + h1v;
    size_t o = (size_t)gid * 2;
    g_Whp[o]     = tf32r(h0v);
    g_Whp[o + 1] = tf32r(h1v);
    g_Wcp[o]     = tf32r(c0v);
    g_Wcp[o + 1] = tf32r(c1v);
}

__global__ void prep_wout(const float* __restrict__ w_out) {
    int gid  = blockIdx.x * 256 + threadIdx.x;     // 1*128*8*32 = 32768 positions
    int lane = gid & 31;
    int nbi  = (gid >> 5) & 7;
    int kc   = gid >> 8;
    int j    = nbi * 8 + (lane >> 2);              // no gate permutation
    int k0   = kc * 8 + (lane & 3);
    const float* r = w_out + (size_t)j * HID;
    size_t o = (size_t)gid * 2;
    g_WoutP[o]     = tf32r(r[k0]);
    g_WoutP[o + 1] = tf32r(r[k0 + 4]);
}

// g0[n'] = dot(start_token, w_ih[j]) + b_ih[j] + b_hh[j]; bp[n'] = b_ih[j]+b_hh[j]
__global__ void prep_bias(const float* __restrict__ st, const float* __restrict__ w_ih,
                          const float* __restrict__ b_ih, const float* __restrict__ b_hh) {
    int gw   = (blockIdx.x * blockDim.x + threadIdx.x) >> 5;
    int lane = threadIdx.x & 31;
    for (int np = gw; np < N4; np += 1024) {
        int h = np >> 2, g = np & 3;
        int j = (g << 10) + h;
        const float* wr = w_ih + (size_t)j * HID;
        float s = 0.f;
        #pragma unroll 8
        for (int k = lane; k < HID; k += 32) s += st[k] * wr[k];
        #pragma unroll
        for (int off = 16; off > 0; off >>= 1) s += __shfl_xor_sync(0xffffffffu, s, off);
        if (lane == 0) {
            float bs = b_ih[j] + b_hh[j];
            g_bp[np] = bs;
            g_g0[np] = s + bs;
        }
    }
}

// ---------------- h0: contraction over input_len, split 4 ways ----------------
__global__ void h0_part(const float* __restrict__ qf, const float* __restrict__ w_in) {
    __shared__ float sw[128];
    int b = blockIdx.x, s = blockIdx.y, tid = threadIdx.x;
    if (tid < 128) sw[tid] = w_in[s * 128 + tid];
    __syncthreads();
    const float4* q = reinterpret_cast<const float4*>(qf)
                    + ((size_t)b * INLEN + s * 128) * (HID / 4) + tid;
    float4 acc = make_float4(0.f, 0.f, 0.f, 0.f);
    #pragma unroll 8
    for (int i = 0; i < 128; i++) {
        float4 v = q[(size_t)i * (HID / 4)];
        float w = sw[i];
        acc.x = fmaf(v.x, w, acc.x);
        acc.y = fmaf(v.y, w, acc.y);
        acc.z = fmaf(v.z, w, acc.z);
        acc.w = fmaf(v.w, w, acc.w);
    }
    g_part4[((size_t)s * BSZ + b) * (HID / 4) + tid] = acc;
}

__global__ void h0_comb(const float* __restrict__ b_in) {
    int b = blockIdx.x, tid = threadIdx.x;
    float4 a = make_float4(0.f, 0.f, 0.f, 0.f);
    #pragma unroll
    for (int s = 0; s < 4; s++) {
        float4 p = g_part4[((size_t)s * BSZ + b) * (HID / 4) + tid];
        a.x += p.x; a.y += p.y; a.z += p.z; a.w += p.w;
    }
    float bb = b_in[0];
    int k = tid * 4;
    g_act0[aperm_idx(b, k + 0)] = tf32r(a.x + bb);
    g_act0[aperm_idx(b, k + 1)] = tf32r(a.y + bb);
    g_act0[aperm_idx(b, k + 2)] = tf32r(a.z + bb);
    g_act0[aperm_idx(b, k + 3)] = tf32r(a.w + bb);
    reinterpret_cast<float4*>(g_c)[(size_t)b * (HID / 4) + tid] =
        make_float4(0.f, 0.f, 0.f, 0.f);
}

// ---------------- fused GEMM (+LSTM cell or +linear) ----------------
// A, W in permuted fragment layouts. mode 0: LSTM step; mode 1: projection.
extern __shared__ float smem[];

__global__ void __launch_bounds__(256, 1)
gemm_step(const float* __restrict__ A, const float* __restrict__ W,
          const float* __restrict__ bias, float* __restrict__ act_out,
          float* __restrict__ dst, int mode, int t) {
    const int tid  = threadIdx.x;
    const int lane = tid & 31;
    const int w    = tid >> 5;
    const int wm   = w & 3;          // 4 m-warps (warp tile 32 rows)
    const int wn   = w >> 2;         // 2 n-warps (warp tile 32 cols)
    const int mt   = blockIdx.x;
    const int nt   = blockIdx.y;
    const int mBase = mt * BM;
    const int nBase = nt * BN;

    const float* Ablk = A + (size_t)mt * A_MT_STRIDE;
    const float* Wblk = W + (size_t)nt * W_NT_STRIDE;

    float acc[2][4][4];
    #pragma unroll
    for (int i = 0; i < 2; i++)
        #pragma unroll
        for (int j = 0; j < 4; j++)
            #pragma unroll
            for (int r = 0; r < 4; r++) acc[i][j][r] = 0.f;

    auto stage = [&](int kt, int slot) {
        float* s = smem + slot * STAGE_F;
        const float* gA = Ablk + (size_t)kt * 4096;   // 4 kc * 8 mb * 32 * 4
        const float* gB = Wblk + (size_t)kt * 2048;   // 4 kc * 8 nb * 32 * 2
        #pragma unroll
        for (int i = 0; i < 4; i++) {
            int c = tid + i * 256;                    // A chunks 0..1023
            cp16(s + c * 4, gA + c * 4);
        }
        #pragma unroll
        for (int i = 0; i < 2; i++) {
            int c = tid + i * 256;                    // B chunks 0..511
            cp16(s + 4096 + c * 4, gB + c * 4);
        }
    };

    stage(0, 0);
    asm volatile("cp.async.commit_group;\n" ::: "memory");
    stage(1, 1);
    asm volatile("cp.async.commit_group;\n" ::: "memory");

    for (int kt = 0; kt < NKT; kt++) {
        if (kt == NKT - 1) asm volatile("cp.async.wait_group 0;\n" ::: "memory");
        else               asm volatile("cp.async.wait_group 1;\n" ::: "memory");
        __syncthreads();
        if (kt + 2 < NKT) {
            stage(kt + 2, (kt + 2) % NSLOT);
            asm volatile("cp.async.commit_group;\n" ::: "memory");
        }
        const int slot = kt % NSLOT;
        const float4* A4 = reinterpret_cast<const float4*>(smem + slot * STAGE_F);
        const float2* B2 = reinterpret_cast<const float2*>(smem + slot * STAGE_F + 4096);

        float4 af[2][2];
        float2 bf[2][4];
        // preload kc=0 fragments
        #pragma unroll
        for (int mb = 0; mb < 2; mb++) af[0][mb] = A4[(wm * 2 + mb) * 32 + lane];
        #pragma unroll
        for (int nb = 0; nb < 4; nb++) bf[0][nb] = B2[(wn * 4 + nb) * 32 + lane];

        #pragma unroll
        for (int kc = 0; kc < 4; kc++) {
            int nxt = (kc + 1) & 1;
            if (kc < 3) {
                #pragma unroll
                for (int mb = 0; mb < 2; mb++)
                    af[nxt][mb] = A4[((kc + 1) * 8 + wm * 2 + mb) * 32 + lane];
                #pragma unroll
                for (int nb = 0; nb < 4; nb++)
                    bf[nxt][nb] = B2[((kc + 1) * 8 + wn * 4 + nb) * 32 + lane];
            }
            int cur = kc & 1;
            #pragma unroll
            for (int mb = 0; mb < 2; mb++)
                #pragma unroll
                for (int nb = 0; nb < 4; nb++)
                    mma_tf32(acc[mb][nb], af[cur][mb], bf[cur][nb]);
        }
    }

    // stash C tile to smem
    __syncthreads();
    float* Cs = smem;
    #pragma unroll
    for (int mb = 0; mb < 2; mb++)
        #pragma unroll
        for (int nb = 0; nb < 4; nb++) {
            int r  = (wm * 2 + mb) * 16 + (lane >> 2);
            int cc = (wn * 4 + nb) * 8 + (lane & 3) * 2;
            Cs[r * CSTRIDE + cc]           = acc[mb][nb][0];
            Cs[r * CSTRIDE + cc + 1]       = acc[mb][nb][1];
            Cs[(r + 8) * CSTRIDE + cc]     = acc[mb][nb][2];
            Cs[(r + 8) * CSTRIDE + cc + 1] = acc[mb][nb][3];
        }
    __syncthreads();

    if (mode == 0) {
        // LSTM cell: 128 rows x 16 h-groups (4 consecutive permuted n = i,f,g,o)
        for (int idx = tid; idx < BM * (BN / 4); idx += 256) {
            int row = idx >> 4, hh = idx & 15;
            int b  = mBase + row;
            int hg = (nBase >> 2) + hh;
            float4 gv = *reinterpret_cast<const float4*>(&Cs[row * CSTRIDE + hh * 4]);
            float4 bb = *reinterpret_cast<const float4*>(&bias[nBase + hh * 4]);
            float gi = gv.x + bb.x;
            float gf = gv.y + bb.y;
            float gg = gv.z + bb.z;
            float go = gv.w + bb.w;
            float cOld = g_c[(size_t)b * HID + hg];
            float cN = sigm(gf) * cOld + sigm(gi) * tanh_acc(gg);
            float hN = sigm(go) * tanh_acc(cN);
            g_c[(size_t)b * HID + hg] = cN;
            g_out[((size_t)b * TSTEPS + t) * HID + hg] = hN;
            float hr = tf32r(hN);
            act_out[aperm_idx(b, hg)] = hr;                    // next-step A
            g_A2[aperm_idx(b * TSTEPS + t, hg)] = hr;          // projection A
        }
    } else {
        for (int idx = tid; idx < BM * BN; idx += 256) {
            int row = idx >> 6, col = idx & 63;
            dst[(size_t)(mBase + row) * OUTW + col] = Cs[row * CSTRIDE + col] + bias[col];
        }
    }
}

// ---------------- host ----------------
extern "C" void kernel_launch(void* const* d_in, const int* in_sizes, int n_in,
                              void* d_out, int out_size) {
    const float* qf    = (const float*)d_in[1];
    const float* st    = (const float*)d_in[4];
    const float* w_in  = (const float*)d_in[5];
    const float* b_in  = (const float*)d_in[6];
    const float* w_ih  = (const float*)d_in[7];
    const float* w_hh  = (const float*)d_in[8];
    const float* b_ih  = (const float*)d_in[9];
    const float* b_hh  = (const float*)d_in[10];
    const float* w_out = (const float*)d_in[11];
    const float* b_out = (const float*)d_in[12];
    float* out = (float*)d_out;

    float *p_Whp, *p_Wcp, *p_WoutP, *p_g0, *p_bp, *p_act0, *p_act1, *p_hout, *p_A2;
    cudaGetSymbolAddress((void**)&p_Whp,   g_Whp);
    cudaGetSymbolAddress((void**)&p_Wcp,   g_Wcp);
    cudaGetSymbolAddress((void**)&p_WoutP, g_WoutP);
    cudaGetSymbolAddress((void**)&p_g0,    g_g0);
    cudaGetSymbolAddress((void**)&p_bp,    g_bp);
    cudaGetSymbolAddress((void**)&p_act0,  g_act0);
    cudaGetSymbolAddress((void**)&p_act1,  g_act1);
    cudaGetSymbolAddress((void**)&p_hout,  g_out);
    cudaGetSymbolAddress((void**)&p_A2,    g_A2);

    cudaFuncSetAttribute(gemm_step, cudaFuncAttributeMaxDynamicSharedMemorySize, SMEM_BYTES);

    prep_weights<<<(N4 * HID / 2) / 256, 256>>>(w_ih, w_hh);
    prep_wout<<<(OUTW * HID / 2) / 256, 256>>>(w_out);
    prep_bias<<<128, 256>>>(st, w_ih, b_ih, b_hh);
    h0_part<<<dim3(BSZ, 4), 256>>>(qf, w_in);
    h0_comb<<<BSZ, 256>>>(b_in);

    // recurrence: 64 fused GEMM+cell steps (ping-pong permuted activations)
    for (int t = 0; t < TSTEPS; t++) {
        const float* Ain  = (t & 1) ? p_act1 : p_act0;
        float*       Aout = (t & 1) ? p_act0 : p_act1;
        const float* Wp   = (t == 0) ? p_Whp : p_Wcp;
        const float* bp   = (t == 0) ? p_g0  : p_bp;
        gemm_step<<<dim3(BSZ / BM, N4 / BN), 256, SMEM_BYTES>>>(
            Ain, Wp, bp, Aout, nullptr, 0, t);
    }

    // outputs: (probs, output)
    const long long PROBS_N = (long long)BSZ * TSTEPS * OUTW;
    const long long OUT_N   = (long long)BSZ * TSTEPS * HID;
    float* probs_dst = nullptr;
    bool copy_hidden = false;
    long long hidden_off = 0;
    if ((long long)out_size >= PROBS_N + OUT_N) {
        probs_dst = out;
        copy_hidden = true;
        hidden_off = PROBS_N;
    } else if ((long long)out_size == OUT_N) {
        copy_hidden = true;
    } else {
        probs_dst = out;
    }

    if (probs_dst) {
        gemm_step<<<dim3((BSZ * TSTEPS) / BM, 1), 256, SMEM_BYTES>>>(
            p_A2, p_WoutP, b_out, nullptr, probs_dst, 1, 0);
    }
    if (copy_hidden) {
        cudaMemcpyAsync(out + hidden_off, p_hout, OUT_N * sizeof(float),
                        cudaMemcpyDeviceToDevice);
    }
}